// round 5
// baseline (speedup 1.0000x reference)
#include <cuda_runtime.h>
#include <cstdint>

#define TILE 128

typedef unsigned long long u64;

// Global accumulator + completion counter. Zero-initialized at module load;
// the last finishing block resets both so CUDA-graph replays are deterministic.
static __device__ double g_acc = 0.0;
static __device__ unsigned int g_count = 0;

__device__ __forceinline__ float frsqrt_(float x) {
    float r; asm("rsqrt.approx.f32 %0, %1;" : "=f"(r) : "f"(x)); return r;
}
__device__ __forceinline__ float fsqrt_(float x) {
    float r; asm("sqrt.approx.f32 %0, %1;" : "=f"(r) : "f"(x)); return r;
}
__device__ __forceinline__ float frcp_(float x) {
    float r; asm("rcp.approx.f32 %0, %1;" : "=f"(r) : "f"(x)); return r;
}

// ---- packed f32x2 helpers ----
__device__ __forceinline__ u64 pk(float lo, float hi) {
    u64 r; asm("mov.b64 %0, {%1, %2};" : "=l"(r) : "f"(lo), "f"(hi)); return r;
}
__device__ __forceinline__ void upk(u64 v, float& lo, float& hi) {
    asm("mov.b64 {%0, %1}, %2;" : "=f"(lo), "=f"(hi) : "l"(v));
}
__device__ __forceinline__ u64 f2fma(u64 a, u64 b, u64 c) {
    u64 r; asm("fma.rn.f32x2 %0, %1, %2, %3;" : "=l"(r) : "l"(a), "l"(b), "l"(c)); return r;
}
__device__ __forceinline__ u64 f2mul(u64 a, u64 b) {
    u64 r; asm("mul.rn.f32x2 %0, %1, %2;" : "=l"(r) : "l"(a), "l"(b)); return r;
}
__device__ __forceinline__ u64 f2add(u64 a, u64 b) {
    u64 r; asm("add.rn.f32x2 %0, %1, %2;" : "=l"(r) : "l"(a), "l"(b)); return r;
}
__device__ __forceinline__ void lds2(uint32_t saddr, u64& a, u64& b) {
    asm volatile("ld.shared.v2.u64 {%0, %1}, [%2];" : "=l"(a), "=l"(b) : "r"(saddr));
}

// Quaternion (qw,qx,qy,qz), UNNORMALIZED (matches reference), row-major R.
__device__ __forceinline__ void quat_to_R(float qw, float qx, float qy, float qz,
                                          float* R) {
    float xx = qx * qx, yy = qy * qy, zz = qz * qz;
    float xy = qx * qy, xz = qx * qz, yz = qy * qz;
    float wx = qw * qx, wy = qw * qy, wz = qw * qz;
    R[0] = 1.0f - 2.0f * yy - 2.0f * zz;
    R[1] = 2.0f * xy - 2.0f * wz;
    R[2] = 2.0f * xz + 2.0f * wy;
    R[3] = 2.0f * xy + 2.0f * wz;
    R[4] = 1.0f - 2.0f * xx - 2.0f * zz;
    R[5] = 2.0f * yz - 2.0f * wx;
    R[6] = 2.0f * xz - 2.0f * wy;
    R[7] = 2.0f * yz + 2.0f * wx;
    R[8] = 1.0f - 2.0f * xx - 2.0f * yy;
}

// Shared field order per m-pair (pair-interleaved SoA, 36 floats/pair):
// 0 -x, 1 -y, 2 -z, 3 R0, 4 R3, 5 R6, 6 R1, 7 R4, 8 R7,
// 9 R2, 10 R5, 11 R8, 12 sx^2, 13 sy^2, 14 sz^2, 15 -vx, 16 -vy, 17 -vz
// field f, half h at p*36 + (f>>1)*4 + (f&1)*2 + h.

__global__ __launch_bounds__(TILE, 6)
void pair_k(const float* __restrict__ xyz, const float* __restrict__ scales,
            const float4* __restrict__ rot4, const float* __restrict__ vel,
            float* __restrict__ out, double inv_norm,
            int N, int T, int TP) {
    __shared__ __align__(16) float shf[TILE * 18];
    __shared__ float warp_sums[TILE / 32];

    int bx = blockIdx.x;
    int b  = bx / TP;
    int t  = bx - b * TP;
    // decode upper-triangular tile pair (i <= j)
    int i = 0;
    while (t >= T - i) { t -= T - i; i++; }
    int j = i + t;

    int tid = threadIdx.x;

    // ---- stage m-tile j into shared (one point per thread) ----
    {
        int m = j * TILE + tid;
        size_t p3 = (size_t)(b * N + m) * 3;
        float4 q = rot4[(size_t)(b * N + m)];
        float R[9];
        quat_to_R(q.x, q.y, q.z, q.w, R);
        float sx = scales[p3 + 0], sy = scales[p3 + 1], sz = scales[p3 + 2];
        float vals[18];
        vals[0]  = -xyz[p3 + 0]; vals[1]  = -xyz[p3 + 1]; vals[2]  = -xyz[p3 + 2];
        vals[3]  = R[0]; vals[4]  = R[3]; vals[5]  = R[6];
        vals[6]  = R[1]; vals[7]  = R[4]; vals[8]  = R[7];
        vals[9]  = R[2]; vals[10] = R[5]; vals[11] = R[8];
        vals[12] = sx * sx; vals[13] = sy * sy; vals[14] = sz * sz;
        vals[15] = -vel[p3 + 0]; vals[16] = -vel[p3 + 1]; vals[17] = -vel[p3 + 2];
        int p = tid >> 1, h = tid & 1;
        float* dstb = &shf[p * 36];
        #pragma unroll
        for (int f = 0; f < 18; f++)
            dstb[(f >> 1) * 4 + (f & 1) * 2 + h] = vals[f];
    }

    // ---- own point n -> packed broadcast constants ----
    u64 xn2, yn2, zn2, vxn2, vyn2, vzn2, s2xn2, s2yn2, s2zn2;
    u64 Rn2[9];
    {
        int n = i * TILE + tid;
        size_t p3 = (size_t)(b * N + n) * 3;
        float4 q = rot4[(size_t)(b * N + n)];
        float Rn[9];
        quat_to_R(q.x, q.y, q.z, q.w, Rn);
        float xn = xyz[p3 + 0], yn = xyz[p3 + 1], zn = xyz[p3 + 2];
        float sx = scales[p3 + 0], sy = scales[p3 + 1], sz = scales[p3 + 2];
        float vx = vel[p3 + 0], vy = vel[p3 + 1], vz = vel[p3 + 2];
        xn2 = pk(xn, xn); yn2 = pk(yn, yn); zn2 = pk(zn, zn);
        vxn2 = pk(vx, vx); vyn2 = pk(vy, vy); vzn2 = pk(vz, vz);
        s2xn2 = pk(sx * sx, sx * sx);
        s2yn2 = pk(sy * sy, sy * sy);
        s2zn2 = pk(sz * sz, sz * sz);
        #pragma unroll
        for (int k = 0; k < 9; k++) Rn2[k] = pk(Rn[k], Rn[k]);
    }
    const u64 eps2 = pk(1e-8f, 1e-8f);

    __syncthreads();

    uint32_t sbase = (uint32_t)__cvta_generic_to_shared(shf);
    float acc = 0.0f;

    #pragma unroll 2
    for (int it = 0; it < TILE / 2; it++) {
        uint32_t sa = sbase + it * 144;   // 36 floats per pair block

        u64 ngx, ngy, ngz, r0m, r3m, r6m, r1m, r4m, r7m, r2m, r5m, r8m;
        u64 s2xm, s2ym, s2zm, nvx, nvy, nvz;
        lds2(sa +   0, ngx, ngy);
        lds2(sa +  16, ngz, r0m);
        lds2(sa +  32, r3m, r6m);

        u64 dx = f2add(xn2, ngx);
        u64 dy = f2add(yn2, ngy);
        u64 dz = f2add(zn2, ngz);
        u64 dd = f2fma(dx, dx, eps2);
        dd = f2fma(dy, dy, dd);
        dd = f2fma(dz, dz, dd);

        lds2(sa +  48, r1m, r4m);
        lds2(sa +  64, r7m, r2m);
        lds2(sa +  80, r5m, r8m);

        // b path: diff @ R_m (columns), scaled by scales_n^2
        u64 b0 = f2mul(dx, r0m); b0 = f2fma(dy, r3m, b0); b0 = f2fma(dz, r6m, b0);
        u64 b1 = f2mul(dx, r1m); b1 = f2fma(dy, r4m, b1); b1 = f2fma(dz, r7m, b1);
        u64 b2 = f2mul(dx, r2m); b2 = f2fma(dy, r5m, b2); b2 = f2fma(dz, r8m, b2);
        u64 s2v = f2mul(f2mul(b0, b0), s2xn2);
        s2v = f2fma(f2mul(b1, b1), s2yn2, s2v);
        s2v = f2fma(f2mul(b2, b2), s2zn2, s2v);

        lds2(sa +  96, s2xm, s2ym);
        lds2(sa + 112, s2zm, nvx);
        lds2(sa + 128, nvy, nvz);

        // a path: diff @ R_n (columns), scaled by scales_m^2
        u64 t0 = f2mul(dx, Rn2[0]); t0 = f2fma(dy, Rn2[3], t0); t0 = f2fma(dz, Rn2[6], t0);
        u64 t1 = f2mul(dx, Rn2[1]); t1 = f2fma(dy, Rn2[4], t1); t1 = f2fma(dz, Rn2[7], t1);
        u64 t2 = f2mul(dx, Rn2[2]); t2 = f2fma(dy, Rn2[5], t2); t2 = f2fma(dz, Rn2[8], t2);
        u64 s1v = f2mul(f2mul(t0, t0), s2xm);
        s1v = f2fma(f2mul(t1, t1), s2ym, s1v);
        s1v = f2fma(f2mul(t2, t2), s2zm, s1v);

        // w = (v_n - v_m) . diff
        u64 rx = f2add(vxn2, nvx);
        u64 ry = f2add(vyn2, nvy);
        u64 rz = f2add(vzn2, nvz);
        u64 w = f2mul(rx, dx);
        w = f2fma(ry, dy, w);
        w = f2fma(rz, dz, w);

        float ddA, ddB, s1A, s1B, s2A, s2B, wA, wB;
        upk(dd, ddA, ddB);
        upk(s1v, s1A, s1B);
        upk(s2v, s2A, s2B);
        upk(w, wA, wB);

        // half A
        {
            float inv = frsqrt_(ddA);
            float rr = fmaxf(fsqrt_(s1A) + fsqrt_(s2A) - ddA, 0.0f);
            float ov = rr * inv;
            float rc = frcp_(fmaf(0.1f, ov, 1.0f));
            float spec = ov * ov * rc;
            float va = wA * inv;
            float hn = fmaxf(-va, 0.0f);
            acc += spec + 0.1f * ov * hn;
        }
        // half B
        {
            float inv = frsqrt_(ddB);
            float rr = fmaxf(fsqrt_(s1B) + fsqrt_(s2B) - ddB, 0.0f);
            float ov = rr * inv;
            float rc = frcp_(fmaf(0.1f, ov, 1.0f));
            float spec = ov * ov * rc;
            float va = wB * inv;
            float hn = fmaxf(-va, 0.0f);
            acc += spec + 0.1f * ov * hn;
        }
    }

    // ---- block reduction ----
    #pragma unroll
    for (int off = 16; off > 0; off >>= 1)
        acc += __shfl_down_sync(0xFFFFFFFFu, acc, off);
    if ((tid & 31) == 0) warp_sums[tid >> 5] = acc;
    __syncthreads();

    if (tid == 0) {
        float s = 0.0f;
        #pragma unroll
        for (int w = 0; w < TILE / 32; w++) s += warp_sums[w];
        float weight = (i == j) ? 1.0f : 2.0f;
        atomicAdd(&g_acc, (double)(s * weight));

        // ---- last-block finalization ----
        __threadfence();
        unsigned int done = atomicAdd(&g_count, 1u);
        if (done == gridDim.x - 1) {
            out[0] = (float)(g_acc * inv_norm);
            g_acc = 0.0;      // reset for next graph replay
            g_count = 0u;
        }
    }
}

extern "C" void kernel_launch(void* const* d_in, const int* in_sizes, int n_in,
                              void* d_out, int out_size) {
    const float* xyz    = (const float*)d_in[0];
    const float* scales = (const float*)d_in[1];
    const float4* rot4  = (const float4*)d_in[2];
    const float* vel    = (const float*)d_in[3];

    int BN = in_sizes[2] / 4;   // rotations: B*N*4
    int N  = 2048;
    if (BN % N != 0) N = BN;
    int B  = BN / N;

    int T  = N / TILE;           // 16 tiles per dim
    int TP = T * (T + 1) / 2;    // 136 upper-tri tile pairs per batch

    double inv_norm = 1.0 / ((double)B * (double)N * (double)N);
    pair_k<<<B * TP, TILE>>>(xyz, scales, rot4, vel, (float*)d_out, inv_norm,
                             N, T, TP);
}

// round 6
// speedup vs baseline: 1.0453x; 1.0453x over previous
#include <cuda_runtime.h>
#include <cstdint>

#define TILE 128

typedef unsigned long long u64;

// Global accumulator + completion counter. Zero-initialized at module load;
// the last finishing block resets both so CUDA-graph replays are deterministic.
static __device__ double g_acc = 0.0;
static __device__ unsigned int g_count = 0;

__device__ __forceinline__ float frsqrt_(float x) {
    float r; asm("rsqrt.approx.f32 %0, %1;" : "=f"(r) : "f"(x)); return r;
}
__device__ __forceinline__ float fsqrt_(float x) {
    float r; asm("sqrt.approx.f32 %0, %1;" : "=f"(r) : "f"(x)); return r;
}
__device__ __forceinline__ float frcp_(float x) {
    float r; asm("rcp.approx.f32 %0, %1;" : "=f"(r) : "f"(x)); return r;
}

// ---- packed f32x2 helpers ----
__device__ __forceinline__ u64 pk(float lo, float hi) {
    u64 r; asm("mov.b64 %0, {%1, %2};" : "=l"(r) : "f"(lo), "f"(hi)); return r;
}
__device__ __forceinline__ void upk(u64 v, float& lo, float& hi) {
    asm("mov.b64 {%0, %1}, %2;" : "=f"(lo), "=f"(hi) : "l"(v));
}
__device__ __forceinline__ u64 f2fma(u64 a, u64 b, u64 c) {
    u64 r; asm("fma.rn.f32x2 %0, %1, %2, %3;" : "=l"(r) : "l"(a), "l"(b), "l"(c)); return r;
}
__device__ __forceinline__ u64 f2mul(u64 a, u64 b) {
    u64 r; asm("mul.rn.f32x2 %0, %1, %2;" : "=l"(r) : "l"(a), "l"(b)); return r;
}
__device__ __forceinline__ u64 f2add(u64 a, u64 b) {
    u64 r; asm("add.rn.f32x2 %0, %1, %2;" : "=l"(r) : "l"(a), "l"(b)); return r;
}
__device__ __forceinline__ void lds2(uint32_t saddr, u64& a, u64& b) {
    asm volatile("ld.shared.v2.u64 {%0, %1}, [%2];" : "=l"(a), "=l"(b) : "r"(saddr));
}

// Quaternion (qw,qx,qy,qz), UNNORMALIZED (matches reference), row-major R.
__device__ __forceinline__ void quat_to_R(float qw, float qx, float qy, float qz,
                                          float* R) {
    float xx = qx * qx, yy = qy * qy, zz = qz * qz;
    float xy = qx * qy, xz = qx * qz, yz = qy * qz;
    float wx = qw * qx, wy = qw * qy, wz = qw * qz;
    R[0] = 1.0f - 2.0f * yy - 2.0f * zz;
    R[1] = 2.0f * xy - 2.0f * wz;
    R[2] = 2.0f * xz + 2.0f * wy;
    R[3] = 2.0f * xy + 2.0f * wz;
    R[4] = 1.0f - 2.0f * xx - 2.0f * zz;
    R[5] = 2.0f * yz - 2.0f * wx;
    R[6] = 2.0f * xz - 2.0f * wy;
    R[7] = 2.0f * yz + 2.0f * wx;
    R[8] = 1.0f - 2.0f * xx - 2.0f * yy;
}

// Shared field order per m-pair (pair-interleaved SoA, 36 floats/pair):
// 0 -x, 1 -y, 2 -z, 3 R0, 4 R3, 5 R6, 6 R1, 7 R4, 8 R7,
// 9 R2, 10 R5, 11 R8, 12 sx^2, 13 sy^2, 14 sz^2, 15 -vx, 16 -vy, 17 -vz
// field f, half h at p*36 + (f>>1)*4 + (f&1)*2 + h.

__global__ __launch_bounds__(TILE)   // NO min-blocks: grid-limited occupancy anyway;
                                     // give ptxas the full register budget.
void pair_k(const float* __restrict__ xyz, const float* __restrict__ scales,
            const float4* __restrict__ rot4, const float* __restrict__ vel,
            float* __restrict__ out, double inv_norm,
            int N, int T, int TP) {
    __shared__ __align__(16) float shf[TILE * 18];
    __shared__ float warp_sums[TILE / 32];

    int bx = blockIdx.x;
    int b  = bx / TP;
    int t  = bx - b * TP;
    // decode upper-triangular tile pair (i <= j)
    int i = 0;
    while (t >= T - i) { t -= T - i; i++; }
    int j = i + t;

    int tid = threadIdx.x;

    // ---- stage m-tile j into shared (one point per thread) ----
    {
        int m = j * TILE + tid;
        size_t p3 = (size_t)(b * N + m) * 3;
        float4 q = rot4[(size_t)(b * N + m)];
        float R[9];
        quat_to_R(q.x, q.y, q.z, q.w, R);
        float sx = scales[p3 + 0], sy = scales[p3 + 1], sz = scales[p3 + 2];
        float vals[18];
        vals[0]  = -xyz[p3 + 0]; vals[1]  = -xyz[p3 + 1]; vals[2]  = -xyz[p3 + 2];
        vals[3]  = R[0]; vals[4]  = R[3]; vals[5]  = R[6];
        vals[6]  = R[1]; vals[7]  = R[4]; vals[8]  = R[7];
        vals[9]  = R[2]; vals[10] = R[5]; vals[11] = R[8];
        vals[12] = sx * sx; vals[13] = sy * sy; vals[14] = sz * sz;
        vals[15] = -vel[p3 + 0]; vals[16] = -vel[p3 + 1]; vals[17] = -vel[p3 + 2];
        int p = tid >> 1, h = tid & 1;
        float* dstb = &shf[p * 36];
        #pragma unroll
        for (int f = 0; f < 18; f++)
            dstb[(f >> 1) * 4 + (f & 1) * 2 + h] = vals[f];
    }

    // ---- own point n -> packed broadcast constants ----
    u64 xn2, yn2, zn2, vxn2, vyn2, vzn2, s2xn2, s2yn2, s2zn2;
    u64 Rn2[9];
    {
        int n = i * TILE + tid;
        size_t p3 = (size_t)(b * N + n) * 3;
        float4 q = rot4[(size_t)(b * N + n)];
        float Rn[9];
        quat_to_R(q.x, q.y, q.z, q.w, Rn);
        float xn = xyz[p3 + 0], yn = xyz[p3 + 1], zn = xyz[p3 + 2];
        float sx = scales[p3 + 0], sy = scales[p3 + 1], sz = scales[p3 + 2];
        float vx = vel[p3 + 0], vy = vel[p3 + 1], vz = vel[p3 + 2];
        xn2 = pk(xn, xn); yn2 = pk(yn, yn); zn2 = pk(zn, zn);
        vxn2 = pk(vx, vx); vyn2 = pk(vy, vy); vzn2 = pk(vz, vz);
        s2xn2 = pk(sx * sx, sx * sx);
        s2yn2 = pk(sy * sy, sy * sy);
        s2zn2 = pk(sz * sz, sz * sz);
        #pragma unroll
        for (int k = 0; k < 9; k++) Rn2[k] = pk(Rn[k], Rn[k]);
    }
    const u64 eps2 = pk(1e-8f, 1e-8f);

    __syncthreads();

    uint32_t sbase = (uint32_t)__cvta_generic_to_shared(shf);
    float acc = 0.0f;

    #pragma unroll 4
    for (int it = 0; it < TILE / 2; it++) {
        uint32_t sa = sbase + it * 144;   // 36 floats per pair block

        u64 ngx, ngy, ngz, r0m, r3m, r6m, r1m, r4m, r7m, r2m, r5m, r8m;
        u64 s2xm, s2ym, s2zm, nvx, nvy, nvz;
        lds2(sa +   0, ngx, ngy);
        lds2(sa +  16, ngz, r0m);
        lds2(sa +  32, r3m, r6m);

        u64 dx = f2add(xn2, ngx);
        u64 dy = f2add(yn2, ngy);
        u64 dz = f2add(zn2, ngz);
        u64 dd = f2fma(dx, dx, eps2);
        dd = f2fma(dy, dy, dd);
        dd = f2fma(dz, dz, dd);

        lds2(sa +  48, r1m, r4m);
        lds2(sa +  64, r7m, r2m);
        lds2(sa +  80, r5m, r8m);

        // b path: diff @ R_m (columns), scaled by scales_n^2
        u64 b0 = f2mul(dx, r0m); b0 = f2fma(dy, r3m, b0); b0 = f2fma(dz, r6m, b0);
        u64 b1 = f2mul(dx, r1m); b1 = f2fma(dy, r4m, b1); b1 = f2fma(dz, r7m, b1);
        u64 b2 = f2mul(dx, r2m); b2 = f2fma(dy, r5m, b2); b2 = f2fma(dz, r8m, b2);
        u64 s2v = f2mul(f2mul(b0, b0), s2xn2);
        s2v = f2fma(f2mul(b1, b1), s2yn2, s2v);
        s2v = f2fma(f2mul(b2, b2), s2zn2, s2v);

        lds2(sa +  96, s2xm, s2ym);
        lds2(sa + 112, s2zm, nvx);
        lds2(sa + 128, nvy, nvz);

        // a path: diff @ R_n (columns), scaled by scales_m^2
        u64 t0 = f2mul(dx, Rn2[0]); t0 = f2fma(dy, Rn2[3], t0); t0 = f2fma(dz, Rn2[6], t0);
        u64 t1 = f2mul(dx, Rn2[1]); t1 = f2fma(dy, Rn2[4], t1); t1 = f2fma(dz, Rn2[7], t1);
        u64 t2 = f2mul(dx, Rn2[2]); t2 = f2fma(dy, Rn2[5], t2); t2 = f2fma(dz, Rn2[8], t2);
        u64 s1v = f2mul(f2mul(t0, t0), s2xm);
        s1v = f2fma(f2mul(t1, t1), s2ym, s1v);
        s1v = f2fma(f2mul(t2, t2), s2zm, s1v);

        // w = (v_n - v_m) . diff
        u64 rx = f2add(vxn2, nvx);
        u64 ry = f2add(vyn2, nvy);
        u64 rz = f2add(vzn2, nvz);
        u64 w = f2mul(rx, dx);
        w = f2fma(ry, dy, w);
        w = f2fma(rz, dz, w);

        float ddA, ddB, s1A, s1B, s2A, s2B, wA, wB;
        upk(dd, ddA, ddB);
        upk(s1v, s1A, s1B);
        upk(s2v, s2A, s2B);
        upk(w, wA, wB);

        // half A
        {
            float inv = frsqrt_(ddA);
            float rr = fmaxf(fsqrt_(s1A) + fsqrt_(s2A) - ddA, 0.0f);
            float ov = rr * inv;
            float rc = frcp_(fmaf(0.1f, ov, 1.0f));
            float spec = ov * ov * rc;
            float va = wA * inv;
            float hn = fmaxf(-va, 0.0f);
            acc += spec + 0.1f * ov * hn;
        }
        // half B
        {
            float inv = frsqrt_(ddB);
            float rr = fmaxf(fsqrt_(s1B) + fsqrt_(s2B) - ddB, 0.0f);
            float ov = rr * inv;
            float rc = frcp_(fmaf(0.1f, ov, 1.0f));
            float spec = ov * ov * rc;
            float va = wB * inv;
            float hn = fmaxf(-va, 0.0f);
            acc += spec + 0.1f * ov * hn;
        }
    }

    // ---- block reduction ----
    #pragma unroll
    for (int off = 16; off > 0; off >>= 1)
        acc += __shfl_down_sync(0xFFFFFFFFu, acc, off);
    if ((tid & 31) == 0) warp_sums[tid >> 5] = acc;
    __syncthreads();

    if (tid == 0) {
        float s = 0.0f;
        #pragma unroll
        for (int w = 0; w < TILE / 32; w++) s += warp_sums[w];
        float weight = (i == j) ? 1.0f : 2.0f;
        atomicAdd(&g_acc, (double)(s * weight));

        // ---- last-block finalization ----
        __threadfence();
        unsigned int done = atomicAdd(&g_count, 1u);
        if (done == gridDim.x - 1) {
            out[0] = (float)(g_acc * inv_norm);
            g_acc = 0.0;      // reset for next graph replay
            g_count = 0u;
        }
    }
}

extern "C" void kernel_launch(void* const* d_in, const int* in_sizes, int n_in,
                              void* d_out, int out_size) {
    const float* xyz    = (const float*)d_in[0];
    const float* scales = (const float*)d_in[1];
    const float4* rot4  = (const float4*)d_in[2];
    const float* vel    = (const float*)d_in[3];

    int BN = in_sizes[2] / 4;   // rotations: B*N*4
    int N  = 2048;
    if (BN % N != 0) N = BN;
    int B  = BN / N;

    int T  = N / TILE;           // 16 tiles per dim
    int TP = T * (T + 1) / 2;    // 136 upper-tri tile pairs per batch

    double inv_norm = 1.0 / ((double)B * (double)N * (double)N);
    pair_k<<<B * TP, TILE>>>(xyz, scales, rot4, vel, (float*)d_out, inv_norm,
                             N, T, TP);
}

// round 9
// speedup vs baseline: 1.0561x; 1.0104x over previous
#include <cuda_runtime.h>
#include <cstdint>

#define TN 128   // n-tile size = threads per block
#define TM 64    // m-half staged per block

typedef unsigned long long u64;

// Global accumulator + completion counter. Zero-initialized at module load;
// the last finishing block resets both so CUDA-graph replays are deterministic.
static __device__ double g_acc = 0.0;
static __device__ unsigned int g_count = 0;

__device__ __forceinline__ float frsqrt_(float x) {
    float r; asm("rsqrt.approx.f32 %0, %1;" : "=f"(r) : "f"(x)); return r;
}
__device__ __forceinline__ float fsqrt_(float x) {
    float r; asm("sqrt.approx.f32 %0, %1;" : "=f"(r) : "f"(x)); return r;
}
__device__ __forceinline__ float frcp_(float x) {
    float r; asm("rcp.approx.f32 %0, %1;" : "=f"(r) : "f"(x)); return r;
}

// ---- packed f32x2 helpers ----
__device__ __forceinline__ u64 pk(float lo, float hi) {
    u64 r; asm("mov.b64 %0, {%1, %2};" : "=l"(r) : "f"(lo), "f"(hi)); return r;
}
__device__ __forceinline__ void upk(u64 v, float& lo, float& hi) {
    asm("mov.b64 {%0, %1}, %2;" : "=f"(lo), "=f"(hi) : "l"(v));
}
__device__ __forceinline__ u64 f2fma(u64 a, u64 b, u64 c) {
    u64 r; asm("fma.rn.f32x2 %0, %1, %2, %3;" : "=l"(r) : "l"(a), "l"(b), "l"(c)); return r;
}
__device__ __forceinline__ u64 f2mul(u64 a, u64 b) {
    u64 r; asm("mul.rn.f32x2 %0, %1, %2;" : "=l"(r) : "l"(a), "l"(b)); return r;
}
__device__ __forceinline__ u64 f2add(u64 a, u64 b) {
    u64 r; asm("add.rn.f32x2 %0, %1, %2;" : "=l"(r) : "l"(a), "l"(b)); return r;
}
__device__ __forceinline__ void lds2(uint32_t saddr, u64& a, u64& b) {
    asm volatile("ld.shared.v2.u64 {%0, %1}, [%2];" : "=l"(a), "=l"(b) : "r"(saddr));
}

// Quaternion (qw,qx,qy,qz), UNNORMALIZED (matches reference), row-major R.
__device__ __forceinline__ void quat_to_R(float qw, float qx, float qy, float qz,
                                          float* R) {
    float xx = qx * qx, yy = qy * qy, zz = qz * qz;
    float xy = qx * qy, xz = qx * qz, yz = qy * qz;
    float wx = qw * qx, wy = qw * qy, wz = qw * qz;
    R[0] = 1.0f - 2.0f * yy - 2.0f * zz;
    R[1] = 2.0f * xy - 2.0f * wz;
    R[2] = 2.0f * xz + 2.0f * wy;
    R[3] = 2.0f * xy + 2.0f * wz;
    R[4] = 1.0f - 2.0f * xx - 2.0f * zz;
    R[5] = 2.0f * yz - 2.0f * wx;
    R[6] = 2.0f * xz - 2.0f * wy;
    R[7] = 2.0f * yz + 2.0f * wx;
    R[8] = 1.0f - 2.0f * xx - 2.0f * yy;
}

// Shared field order per m-pair (pair-interleaved SoA, 36 floats/pair):
// 0 -x, 1 -y, 2 -z, 3 R0, 4 R3, 5 R6, 6 R1, 7 R4, 8 R7,
// 9 R2, 10 R5, 11 R8, 12 sx^2, 13 sy^2, 14 sz^2, 15 -vx, 16 -vy, 17 -vz
// field f, half h at p*36 + (f>>1)*4 + (f&1)*2 + h.

__global__ __launch_bounds__(TN)
void pair_k(const float* __restrict__ xyz, const float* __restrict__ scales,
            const float4* __restrict__ rot4, const float* __restrict__ vel,
            float* __restrict__ out, double inv_norm,
            int N, int T, int TP2) {
    __shared__ __align__(16) float shf[TM * 18];
    __shared__ float warp_sums[TN / 32];

    int bx = blockIdx.x;
    int b  = bx / TP2;
    int r  = bx - b * TP2;
    int t  = r >> 1;
    int half = r & 1;
    // decode upper-triangular tile pair (i <= j), tiles of TN
    int i = 0;
    while (t >= T - i) { t -= T - i; i++; }
    int j = i + t;

    int tid = threadIdx.x;

    // ---- stage m-half (64 points) into shared: first 64 threads, 1 pt each ----
    if (tid < TM) {
        int m = j * TN + half * TM + tid;
        size_t p3 = (size_t)(b * N + m) * 3;
        float4 q = rot4[(size_t)(b * N + m)];
        float R[9];
        quat_to_R(q.x, q.y, q.z, q.w, R);
        float sx = scales[p3 + 0], sy = scales[p3 + 1], sz = scales[p3 + 2];
        float vals[18];
        vals[0]  = -xyz[p3 + 0]; vals[1]  = -xyz[p3 + 1]; vals[2]  = -xyz[p3 + 2];
        vals[3]  = R[0]; vals[4]  = R[3]; vals[5]  = R[6];
        vals[6]  = R[1]; vals[7]  = R[4]; vals[8]  = R[7];
        vals[9]  = R[2]; vals[10] = R[5]; vals[11] = R[8];
        vals[12] = sx * sx; vals[13] = sy * sy; vals[14] = sz * sz;
        vals[15] = -vel[p3 + 0]; vals[16] = -vel[p3 + 1]; vals[17] = -vel[p3 + 2];
        int p = tid >> 1, h = tid & 1;
        float* dstb = &shf[p * 36];
        #pragma unroll
        for (int f = 0; f < 18; f++)
            dstb[(f >> 1) * 4 + (f & 1) * 2 + h] = vals[f];
    }

    // ---- own point n -> packed broadcast constants ----
    u64 xn2, yn2, zn2, vxn2, vyn2, vzn2, s2xn2, s2yn2, s2zn2;
    u64 Rn2[9];
    {
        int n = i * TN + tid;
        size_t p3 = (size_t)(b * N + n) * 3;
        float4 q = rot4[(size_t)(b * N + n)];
        float Rn[9];
        quat_to_R(q.x, q.y, q.z, q.w, Rn);
        float xn = xyz[p3 + 0], yn = xyz[p3 + 1], zn = xyz[p3 + 2];
        float sx = scales[p3 + 0], sy = scales[p3 + 1], sz = scales[p3 + 2];
        float vx = vel[p3 + 0], vy = vel[p3 + 1], vz = vel[p3 + 2];
        xn2 = pk(xn, xn); yn2 = pk(yn, yn); zn2 = pk(zn, zn);
        vxn2 = pk(vx, vx); vyn2 = pk(vy, vy); vzn2 = pk(vz, vz);
        s2xn2 = pk(sx * sx, sx * sx);
        s2yn2 = pk(sy * sy, sy * sy);
        s2zn2 = pk(sz * sz, sz * sz);
        #pragma unroll
        for (int k = 0; k < 9; k++) Rn2[k] = pk(Rn[k], Rn[k]);
    }
    const u64 eps2 = pk(1e-8f, 1e-8f);

    __syncthreads();

    uint32_t sbase = (uint32_t)__cvta_generic_to_shared(shf);
    float acc = 0.0f;

    #pragma unroll 2
    for (int it = 0; it < TM / 2; it++) {
        uint32_t sa = sbase + it * 144;   // 36 floats per pair block

        u64 ngx, ngy, ngz, r0m, r3m, r6m, r1m, r4m, r7m, r2m, r5m, r8m;
        u64 s2xm, s2ym, s2zm, nvx, nvy, nvz;
        lds2(sa +   0, ngx, ngy);
        lds2(sa +  16, ngz, r0m);
        lds2(sa +  32, r3m, r6m);

        u64 dx = f2add(xn2, ngx);
        u64 dy = f2add(yn2, ngy);
        u64 dz = f2add(zn2, ngz);
        u64 dd = f2fma(dx, dx, eps2);
        dd = f2fma(dy, dy, dd);
        dd = f2fma(dz, dz, dd);

        lds2(sa +  48, r1m, r4m);
        lds2(sa +  64, r7m, r2m);
        lds2(sa +  80, r5m, r8m);

        // b path: diff @ R_m (columns), scaled by scales_n^2
        u64 b0 = f2mul(dx, r0m); b0 = f2fma(dy, r3m, b0); b0 = f2fma(dz, r6m, b0);
        u64 b1 = f2mul(dx, r1m); b1 = f2fma(dy, r4m, b1); b1 = f2fma(dz, r7m, b1);
        u64 b2 = f2mul(dx, r2m); b2 = f2fma(dy, r5m, b2); b2 = f2fma(dz, r8m, b2);
        u64 s2v = f2mul(f2mul(b0, b0), s2xn2);
        s2v = f2fma(f2mul(b1, b1), s2yn2, s2v);
        s2v = f2fma(f2mul(b2, b2), s2zn2, s2v);

        lds2(sa +  96, s2xm, s2ym);
        lds2(sa + 112, s2zm, nvx);
        lds2(sa + 128, nvy, nvz);

        // a path: diff @ R_n (columns), scaled by scales_m^2
        u64 t0 = f2mul(dx, Rn2[0]); t0 = f2fma(dy, Rn2[3], t0); t0 = f2fma(dz, Rn2[6], t0);
        u64 t1 = f2mul(dx, Rn2[1]); t1 = f2fma(dy, Rn2[4], t1); t1 = f2fma(dz, Rn2[7], t1);
        u64 t2 = f2mul(dx, Rn2[2]); t2 = f2fma(dy, Rn2[5], t2); t2 = f2fma(dz, Rn2[8], t2);
        u64 s1v = f2mul(f2mul(t0, t0), s2xm);
        s1v = f2fma(f2mul(t1, t1), s2ym, s1v);
        s1v = f2fma(f2mul(t2, t2), s2zm, s1v);

        // w = (v_n - v_m) . diff
        u64 rx = f2add(vxn2, nvx);
        u64 ry = f2add(vyn2, nvy);
        u64 rz = f2add(vzn2, nvz);
        u64 w = f2mul(rx, dx);
        w = f2fma(ry, dy, w);
        w = f2fma(rz, dz, w);

        float ddA, ddB, s1A, s1B, s2A, s2B, wA, wB;
        upk(dd, ddA, ddB);
        upk(s1v, s1A, s1B);
        upk(s2v, s2A, s2B);
        upk(w, wA, wB);

        // epilogue per half: factored form
        // acc += ov*(ov*rc + 0.1*hn);  hn = relu(-w*inv);  ov = relu(q1+q2-dd)*inv
        {
            float inv = frsqrt_(ddA);
            float q1 = fsqrt_(s1A);
            float q2 = fsqrt_(s2A);
            float ssum = (q1 - ddA) + q2;
            float rr = fmaxf(ssum, 0.0f);          // FMNMX (alu pipe)
            float ov = rr * inv;
            float rc = frcp_(fmaf(0.1f, ov, 1.0f)); // imm-fma rt1
            float tva = wA * inv;
            float hn = fmaxf(-tva, 0.0f);          // FMNMX (alu pipe)
            float inner = fmaf(ov, rc, 0.1f * hn);
            acc = fmaf(ov, inner, acc);
        }
        {
            float inv = frsqrt_(ddB);
            float q1 = fsqrt_(s1B);
            float q2 = fsqrt_(s2B);
            float ssum = (q1 - ddB) + q2;
            float rr = fmaxf(ssum, 0.0f);
            float ov = rr * inv;
            float rc = frcp_(fmaf(0.1f, ov, 1.0f));
            float tva = wB * inv;
            float hn = fmaxf(-tva, 0.0f);
            float inner = fmaf(ov, rc, 0.1f * hn);
            acc = fmaf(ov, inner, acc);
        }
    }

    // ---- block reduction ----
    #pragma unroll
    for (int off = 16; off > 0; off >>= 1)
        acc += __shfl_down_sync(0xFFFFFFFFu, acc, off);
    if ((tid & 31) == 0) warp_sums[tid >> 5] = acc;
    __syncthreads();

    if (tid == 0) {
        float s = 0.0f;
        #pragma unroll
        for (int w = 0; w < TN / 32; w++) s += warp_sums[w];
        float weight = (i == j) ? 1.0f : 2.0f;
        atomicAdd(&g_acc, (double)(s * weight));

        // ---- last-block finalization ----
        __threadfence();
        unsigned int done = atomicAdd(&g_count, 1u);
        if (done == gridDim.x - 1) {
            out[0] = (float)(g_acc * inv_norm);
            g_acc = 0.0;      // reset for next graph replay
            g_count = 0u;
        }
    }
}

extern "C" void kernel_launch(void* const* d_in, const int* in_sizes, int n_in,
                              void* d_out, int out_size) {
    const float* xyz    = (const float*)d_in[0];
    const float* scales = (const float*)d_in[1];
    const float4* rot4  = (const float4*)d_in[2];
    const float* vel    = (const float*)d_in[3];

    int BN = in_sizes[2] / 4;   // rotations: B*N*4
    int N  = 2048;
    if (BN % N != 0) N = BN;
    int B  = BN / N;

    int T   = N / TN;            // 16 n-tiles
    int TP  = T * (T + 1) / 2;   // 136 upper-tri tile pairs
    int TP2 = TP * 2;            // 2 m-halves per tile pair

    double inv_norm = 1.0 / ((double)B * (double)N * (double)N);
    pair_k<<<B * TP2, TN>>>(xyz, scales, rot4, vel, (float*)d_out, inv_norm,
                            N, T, TP2);
}

// round 10
// speedup vs baseline: 1.0960x; 1.0378x over previous
#include <cuda_runtime.h>
#include <cstdint>

#define TN 128    // threads per block
#define NW 256    // n-strip width (2 n-points per thread)
#define TM 64     // m-quarter staged per block

typedef unsigned long long u64;

static __device__ double g_acc = 0.0;
static __device__ unsigned int g_count = 0;

__device__ __forceinline__ float frsqrt_(float x) {
    float r; asm("rsqrt.approx.f32 %0, %1;" : "=f"(r) : "f"(x)); return r;
}
__device__ __forceinline__ float fsqrt_(float x) {
    float r; asm("sqrt.approx.f32 %0, %1;" : "=f"(r) : "f"(x)); return r;
}
__device__ __forceinline__ float frcp_(float x) {
    float r; asm("rcp.approx.f32 %0, %1;" : "=f"(r) : "f"(x)); return r;
}

__device__ __forceinline__ u64 pk(float lo, float hi) {
    u64 r; asm("mov.b64 %0, {%1, %2};" : "=l"(r) : "f"(lo), "f"(hi)); return r;
}
__device__ __forceinline__ void upk(u64 v, float& lo, float& hi) {
    asm("mov.b64 {%0, %1}, %2;" : "=f"(lo), "=f"(hi) : "l"(v));
}
__device__ __forceinline__ u64 f2fma(u64 a, u64 b, u64 c) {
    u64 r; asm("fma.rn.f32x2 %0, %1, %2, %3;" : "=l"(r) : "l"(a), "l"(b), "l"(c)); return r;
}
__device__ __forceinline__ u64 f2mul(u64 a, u64 b) {
    u64 r; asm("mul.rn.f32x2 %0, %1, %2;" : "=l"(r) : "l"(a), "l"(b)); return r;
}
__device__ __forceinline__ u64 f2add(u64 a, u64 b) {
    u64 r; asm("add.rn.f32x2 %0, %1, %2;" : "=l"(r) : "l"(a), "l"(b)); return r;
}
__device__ __forceinline__ void lds2(uint32_t saddr, u64& a, u64& b) {
    asm volatile("ld.shared.v2.u64 {%0, %1}, [%2];" : "=l"(a), "=l"(b) : "r"(saddr));
}

// Quaternion (qw,qx,qy,qz), UNNORMALIZED (matches reference), row-major R.
__device__ __forceinline__ void quat_to_R(float qw, float qx, float qy, float qz,
                                          float* R) {
    float xx = qx * qx, yy = qy * qy, zz = qz * qz;
    float xy = qx * qy, xz = qx * qz, yz = qy * qz;
    float wx = qw * qx, wy = qw * qy, wz = qw * qz;
    R[0] = 1.0f - 2.0f * yy - 2.0f * zz;
    R[1] = 2.0f * xy - 2.0f * wz;
    R[2] = 2.0f * xz + 2.0f * wy;
    R[3] = 2.0f * xy + 2.0f * wz;
    R[4] = 1.0f - 2.0f * xx - 2.0f * zz;
    R[5] = 2.0f * yz - 2.0f * wx;
    R[6] = 2.0f * xz - 2.0f * wy;
    R[7] = 2.0f * yz + 2.0f * wx;
    R[8] = 1.0f - 2.0f * xx - 2.0f * yy;
}

// Shared field order per m-pair (pair-interleaved SoA, 36 floats/pair):
// 0 -x, 1 -y, 2 -z, 3 R0, 4 R3, 5 R6, 6 R1, 7 R4, 8 R7,
// 9 R2, 10 R5, 11 R8, 12 sx^2, 13 sy^2, 14 sz^2, 15 -vx, 16 -vy, 17 -vz

__global__ __launch_bounds__(TN)
void pair_k(const float* __restrict__ xyz, const float* __restrict__ scales,
            const float4* __restrict__ rot4, const float* __restrict__ vel,
            float* __restrict__ out, double inv_norm,
            int N, int T, int TP4) {
    __shared__ __align__(16) float shf[TM * 18];
    __shared__ float warp_sums[TN / 32];

    int bx = blockIdx.x;
    int b  = bx / TP4;
    int r  = bx - b * TP4;
    int t  = r >> 2;
    int quarter = r & 3;
    // decode upper-triangular strip pair (i <= j) over T strips of width NW
    int i = 0;
    while (t >= T - i) { t -= T - i; i++; }
    int j = i + t;

    int tid = threadIdx.x;

    // ---- stage m-quarter (64 points) into shared: first 64 threads ----
    if (tid < TM) {
        int m = j * NW + quarter * TM + tid;
        size_t p3 = (size_t)(b * N + m) * 3;
        float4 q = rot4[(size_t)(b * N + m)];
        float R[9];
        quat_to_R(q.x, q.y, q.z, q.w, R);
        float sx = scales[p3 + 0], sy = scales[p3 + 1], sz = scales[p3 + 2];
        float vals[18];
        vals[0]  = -xyz[p3 + 0]; vals[1]  = -xyz[p3 + 1]; vals[2]  = -xyz[p3 + 2];
        vals[3]  = R[0]; vals[4]  = R[3]; vals[5]  = R[6];
        vals[6]  = R[1]; vals[7]  = R[4]; vals[8]  = R[7];
        vals[9]  = R[2]; vals[10] = R[5]; vals[11] = R[8];
        vals[12] = sx * sx; vals[13] = sy * sy; vals[14] = sz * sz;
        vals[15] = -vel[p3 + 0]; vals[16] = -vel[p3 + 1]; vals[17] = -vel[p3 + 2];
        int p = tid >> 1, h = tid & 1;
        float* dstb = &shf[p * 36];
        #pragma unroll
        for (int f = 0; f < 18; f++)
            dstb[(f >> 1) * 4 + (f & 1) * 2 + h] = vals[f];
    }

    // ---- own 2 n-points -> packed broadcast constants ----
    u64 xn2[2], yn2[2], zn2[2], vxn2[2], vyn2[2], vzn2[2];
    u64 s2xn2[2], s2yn2[2], s2zn2[2];
    u64 Rn2[2][9];
    #pragma unroll
    for (int u = 0; u < 2; u++) {
        int n = i * NW + u * TN + tid;
        size_t p3 = (size_t)(b * N + n) * 3;
        float4 q = rot4[(size_t)(b * N + n)];
        float Rn[9];
        quat_to_R(q.x, q.y, q.z, q.w, Rn);
        float xn = xyz[p3 + 0], yn = xyz[p3 + 1], zn = xyz[p3 + 2];
        float sx = scales[p3 + 0], sy = scales[p3 + 1], sz = scales[p3 + 2];
        float vx = vel[p3 + 0], vy = vel[p3 + 1], vz = vel[p3 + 2];
        xn2[u] = pk(xn, xn); yn2[u] = pk(yn, yn); zn2[u] = pk(zn, zn);
        vxn2[u] = pk(vx, vx); vyn2[u] = pk(vy, vy); vzn2[u] = pk(vz, vz);
        s2xn2[u] = pk(sx * sx, sx * sx);
        s2yn2[u] = pk(sy * sy, sy * sy);
        s2zn2[u] = pk(sz * sz, sz * sz);
        #pragma unroll
        for (int k = 0; k < 9; k++) Rn2[u][k] = pk(Rn[k], Rn[k]);
    }
    const u64 eps2 = pk(1e-8f, 1e-8f);

    __syncthreads();

    uint32_t sbase = (uint32_t)__cvta_generic_to_shared(shf);
    float acc = 0.0f;

    #pragma unroll 2
    for (int it = 0; it < TM / 2; it++) {
        uint32_t sa = sbase + it * 144;

        u64 ngx, ngy, ngz, r0m, r3m, r6m, r1m, r4m, r7m, r2m, r5m, r8m;
        u64 s2xm, s2ym, s2zm, nvx, nvy, nvz;
        lds2(sa +   0, ngx, ngy);
        lds2(sa +  16, ngz, r0m);
        lds2(sa +  32, r3m, r6m);
        lds2(sa +  48, r1m, r4m);
        lds2(sa +  64, r7m, r2m);
        lds2(sa +  80, r5m, r8m);
        lds2(sa +  96, s2xm, s2ym);
        lds2(sa + 112, s2zm, nvx);
        lds2(sa + 128, nvy, nvz);

        #pragma unroll
        for (int u = 0; u < 2; u++) {
            u64 dx = f2add(xn2[u], ngx);
            u64 dy = f2add(yn2[u], ngy);
            u64 dz = f2add(zn2[u], ngz);
            u64 dd = f2fma(dx, dx, eps2);
            dd = f2fma(dy, dy, dd);
            dd = f2fma(dz, dz, dd);

            // b path: diff @ R_m columns, scaled by scales_n^2
            u64 b0 = f2mul(dx, r0m); b0 = f2fma(dy, r3m, b0); b0 = f2fma(dz, r6m, b0);
            u64 b1 = f2mul(dx, r1m); b1 = f2fma(dy, r4m, b1); b1 = f2fma(dz, r7m, b1);
            u64 b2 = f2mul(dx, r2m); b2 = f2fma(dy, r5m, b2); b2 = f2fma(dz, r8m, b2);
            u64 s2v = f2mul(f2mul(b0, b0), s2xn2[u]);
            s2v = f2fma(f2mul(b1, b1), s2yn2[u], s2v);
            s2v = f2fma(f2mul(b2, b2), s2zn2[u], s2v);

            // a path: diff @ R_n columns, scaled by scales_m^2
            u64 t0 = f2mul(dx, Rn2[u][0]); t0 = f2fma(dy, Rn2[u][3], t0); t0 = f2fma(dz, Rn2[u][6], t0);
            u64 t1 = f2mul(dx, Rn2[u][1]); t1 = f2fma(dy, Rn2[u][4], t1); t1 = f2fma(dz, Rn2[u][7], t1);
            u64 t2 = f2mul(dx, Rn2[u][2]); t2 = f2fma(dy, Rn2[u][5], t2); t2 = f2fma(dz, Rn2[u][8], t2);
            u64 s1v = f2mul(f2mul(t0, t0), s2xm);
            s1v = f2fma(f2mul(t1, t1), s2ym, s1v);
            s1v = f2fma(f2mul(t2, t2), s2zm, s1v);

            // w = (v_n - v_m) . diff
            u64 rx = f2add(vxn2[u], nvx);
            u64 ry = f2add(vyn2[u], nvy);
            u64 rz = f2add(vzn2[u], nvz);
            u64 w = f2mul(rx, dx);
            w = f2fma(ry, dy, w);
            w = f2fma(rz, dz, w);

            float ddA, ddB, s1A, s1B, s2A, s2B, wA, wB;
            upk(dd, ddA, ddB);
            upk(s1v, s1A, s1B);
            upk(s2v, s2A, s2B);
            upk(w, wA, wB);

            {
                float inv = frsqrt_(ddA);
                float ssum = (fsqrt_(s1A) - ddA) + fsqrt_(s2A);
                float rr = fmaxf(ssum, 0.0f);
                float ov = rr * inv;
                float rc = frcp_(fmaf(0.1f, ov, 1.0f));
                float hn = fmaxf(-(wA * inv), 0.0f);
                float inner = fmaf(ov, rc, 0.1f * hn);
                acc = fmaf(ov, inner, acc);
            }
            {
                float inv = frsqrt_(ddB);
                float ssum = (fsqrt_(s1B) - ddB) + fsqrt_(s2B);
                float rr = fmaxf(ssum, 0.0f);
                float ov = rr * inv;
                float rc = frcp_(fmaf(0.1f, ov, 1.0f));
                float hn = fmaxf(-(wB * inv), 0.0f);
                float inner = fmaf(ov, rc, 0.1f * hn);
                acc = fmaf(ov, inner, acc);
            }
        }
    }

    // ---- block reduction ----
    #pragma unroll
    for (int off = 16; off > 0; off >>= 1)
        acc += __shfl_down_sync(0xFFFFFFFFu, acc, off);
    if ((tid & 31) == 0) warp_sums[tid >> 5] = acc;
    __syncthreads();

    if (tid == 0) {
        float s = 0.0f;
        #pragma unroll
        for (int w = 0; w < TN / 32; w++) s += warp_sums[w];
        float weight = (i == j) ? 1.0f : 2.0f;
        atomicAdd(&g_acc, (double)(s * weight));

        __threadfence();
        unsigned int done = atomicAdd(&g_count, 1u);
        if (done == gridDim.x - 1) {
            out[0] = (float)(g_acc * inv_norm);
            g_acc = 0.0;
            g_count = 0u;
        }
    }
}

extern "C" void kernel_launch(void* const* d_in, const int* in_sizes, int n_in,
                              void* d_out, int out_size) {
    const float* xyz    = (const float*)d_in[0];
    const float* scales = (const float*)d_in[1];
    const float4* rot4  = (const float4*)d_in[2];
    const float* vel    = (const float*)d_in[3];

    int BN = in_sizes[2] / 4;   // rotations: B*N*4
    int N  = 2048;
    if (BN % N != 0) N = BN;
    int B  = BN / N;

    int T   = N / NW;            // 8 n-strips of 256
    int TP  = T * (T + 1) / 2;   // 36 upper-tri strip pairs
    int TP4 = TP * 4;            // 4 m-quarters per strip pair

    double inv_norm = 1.0 / ((double)B * (double)N * (double)N);
    pair_k<<<B * TP4, TN>>>(xyz, scales, rot4, vel, (float*)d_out, inv_norm,
                            N, T, TP4);
}